// round 14
// baseline (speedup 1.0000x reference)
#include <cuda_runtime.h>
#include <math.h>

#define SUB_NO 20
#define T_NO   201
#define T_DATA 100000
#define E_NO   800
#define I_NO   200

#define FKP     208            // flipped kernel row, padded (zeros at 201..207)
#define NGROUP  52             // FKP/4 tap groups

#define GRID    148            // <= SM count; 1 block/SM -> all co-resident
#define THREADS 640
#define NAGG    88             // agg-role blocks; rest start as fir consumers

#define AGG_T     16           // t rows per tile
#define AGG_TILES (T_DATA / AGG_T)     // 6250
#define SEG_TILES 640                  // tiles per fir segment (10240 t)
#define NSEG      10
#define EPAD 804
#define IPAD 204
#define BUF_FLOATS (AGG_T * EPAD + AGG_T * IPAD)   // 16128
#define NBUF 3

#define F_T   10240            // fir outputs per job (640 thr x 16)
#define F_WIN 10448            // 10240 + 200 halo + 8 pad
#define NJOB  (2 * SUB_NO * NSEG)      // 400, seg-major

#define DYN_SMEM ((NBUF * BUF_FLOATS + E_NO + I_NO) * 4)   // ~193KB

typedef unsigned long long u64;

__device__ __forceinline__ u64 pk2(float lo, float hi) {
    u64 r; asm("mov.b64 %0, {%1, %2};" : "=l"(r) : "f"(lo), "f"(hi)); return r;
}
__device__ __forceinline__ void upk2(u64 p, float& lo, float& hi) {
    asm("mov.b64 {%0, %1}, %2;" : "=f"(lo), "=f"(hi) : "l"(p));
}
__device__ __forceinline__ void ffma2(u64& d, u64 a, u64 b) {
    asm("fma.rn.f32x2 %0, %1, %2, %0;" : "+l"(d) : "l"(a), "l"(b));
}
__device__ __forceinline__ void cp16(unsigned dst, const float* src) {
    asm volatile("cp.async.cg.shared.global [%0], [%1], 16;" :: "r"(dst), "l"(src));
}
// release/acquire primitives — NO CCTL.IVALL (never flush L1 near cp.async)
__device__ __forceinline__ void red_release_add(unsigned* p, unsigned v) {
    asm volatile("red.release.gpu.add.u32 [%0], %1;" :: "l"(p), "r"(v) : "memory");
}
__device__ __forceinline__ unsigned atom_add_release(unsigned* p, unsigned v) {
    unsigned old;
    asm volatile("atom.add.release.gpu.u32 %0, [%1], %2;"
                 : "=r"(old) : "l"(p), "r"(v) : "memory");
    return old;
}
__device__ __forceinline__ unsigned ld_acquire(unsigned* p) {
    unsigned v;
    asm volatile("ld.acquire.gpu.u32 %0, [%1];" : "=r"(v) : "l"(p) : "memory");
    return v;
}

// -------- device scratch / sync state (no allocations allowed) --------
__device__ float g_syn_e[SUB_NO * T_DATA];
__device__ float g_syn_i[SUB_NO * T_DATA];
__device__ float g_fir_e[SUB_NO * T_DATA];
__device__ float g_fir_i[SUB_NO * T_DATA];
__device__ float g_fk2[2 * SUB_NO * 2 * FKP];
__device__ int   g_elist[E_NO];
__device__ int   g_ilist[I_NO];
__device__ int   g_eoff[SUB_NO + 1];
__device__ int   g_ioff[SUB_NO + 1];
__device__ unsigned g_cnt[NSEG];     // tiles completed per segment (0 at launch)
__device__ unsigned g_job;           // fir job ticket (0 at launch)
__device__ unsigned g_bar_cnt;       // barrier arrivals (self-resetting)
__device__ unsigned g_bar_sense;     // barrier sense (monotonic, never reset)

// ================= K0: setup (lists, alpha kernels, filters out) ===========
__global__ void __launch_bounds__(512)
k_setup(const float* __restrict__ Cse, const float* __restrict__ Csi,
        const float* __restrict__ Wsyn, const float* __restrict__ Tau,
        const float* __restrict__ Delta,
        float* __restrict__ out_filters) {
    __shared__ int s_ae[E_NO];
    __shared__ int s_ai[I_NO];
    __shared__ int s_cnt_e[SUB_NO], s_cnt_i[SUB_NO];
    __shared__ int s_off_e[SUB_NO + 1], s_off_i[SUB_NO + 1];
    const int tid = threadIdx.x;

    for (int idx = tid; idx < 2 * SUB_NO * T_NO; idx += blockDim.x) {
        int t  = idx % T_NO;
        int sc = idx / T_NO;
        int c  = sc / SUB_NO;
        int s  = sc % SUB_NO;
        float v = 0.f;
        #pragma unroll
        for (int j = 0; j < 2; j++) {
            float W   = Wsyn [(s * 2 + j) * 2 + c];
            float tau = Tau  [(s * 2 + j) * 2 + c];
            float dl  = Delta[(s * 2 + j) * 2 + c];
            float td  = fmaxf((float)t - dl, 0.f);
            float tt  = td * expf(-tau);
            v += tt * expf(-tt) * W;
        }
        out_filters[sc * T_NO + t] = v;
        int u = T_NO - 1 - t;
        g_fk2[sc * 2 * FKP + 2 * u]     = v;
        g_fk2[sc * 2 * FKP + 2 * u + 1] = v;
    }
    for (int idx = tid; idx < 2 * SUB_NO * (FKP - T_NO); idx += blockDim.x) {
        int sc = idx / (FKP - T_NO);
        int p  = idx % (FKP - T_NO);
        int u  = T_NO + p;
        g_fk2[sc * 2 * FKP + 2 * u]     = 0.f;
        g_fk2[sc * 2 * FKP + 2 * u + 1] = 0.f;
    }

    if (tid < SUB_NO) { s_cnt_e[tid] = 0; s_cnt_i[tid] = 0; }
    __syncthreads();
    for (int e = tid; e < E_NO; e += blockDim.x) {
        int a = 0;
        #pragma unroll
        for (int s = 0; s < SUB_NO; s++) a += s * (Cse[s * E_NO + e] > 0.5f);
        s_ae[e] = a;
        atomicAdd(&s_cnt_e[a], 1);
    }
    for (int i = tid; i < I_NO; i += blockDim.x) {
        int a = 0;
        #pragma unroll
        for (int s = 0; s < SUB_NO; s++) a += s * (Csi[s * I_NO + i] > 0.5f);
        s_ai[i] = a;
        atomicAdd(&s_cnt_i[a], 1);
    }
    __syncthreads();
    if (tid == 0) {
        int acc = 0;
        for (int s = 0; s < SUB_NO; s++) { s_off_e[s] = acc; acc += s_cnt_e[s]; }
        s_off_e[SUB_NO] = acc;
        acc = 0;
        for (int s = 0; s < SUB_NO; s++) { s_off_i[s] = acc; acc += s_cnt_i[s]; }
        s_off_i[SUB_NO] = acc;
    }
    __syncthreads();
    for (int e = tid; e < E_NO; e += blockDim.x) {
        int a = s_ae[e], r = 0;
        for (int p = 0; p < e; p++) r += (s_ae[p] == a);
        g_elist[s_off_e[a] + r] = e;
    }
    for (int i = tid; i < I_NO; i += blockDim.x) {
        int a = s_ai[i], r = 0;
        for (int p = 0; p < i; p++) r += (s_ai[p] == a);
        g_ilist[s_off_i[a] + r] = i;
    }
    if (tid <= SUB_NO) { g_eoff[tid] = s_off_e[tid]; g_ioff[tid] = s_off_i[tid]; }
}

// ================= K1: fused persistent agg + fir + tree ==================
__global__ void __launch_bounds__(THREADS, 1)
k_main(const float* __restrict__ S_e, const float* __restrict__ S_i,
       const float* __restrict__ C_den, const float* __restrict__ W_sub,
       const float* __restrict__ Theta, const float* __restrict__ V_o,
       const float* __restrict__ Cse, const float* __restrict__ Csi,
       float* __restrict__ out_v) {
    extern __shared__ float sh[];
    __shared__ int sjob;
    __shared__ float cw[SUB_NO * SUB_NO];
    __shared__ float th[SUB_NO];
    const int tid = threadIdx.x;
    const int bid = blockIdx.x;

    // ---------------- phase A: aggregation (blocks 0..NAGG-1) -------------
    if (bid < NAGG) {
        int* s_el = (int*)(sh + NBUF * BUF_FLOATS);
        int* s_il = s_el + E_NO;
        const int w  = tid >> 5;
        const int l  = tid & 31;
        const int lr = l & 15;

        for (int q = tid; q < E_NO; q += THREADS) s_el[q] = g_elist[q];
        for (int q = tid; q < I_NO; q += THREADS) s_il[q] = g_ilist[q];
        const int be = g_eoff[w], ee = g_eoff[w + 1];
        const int bi = g_ioff[w], ei = g_ioff[w + 1];

        unsigned sb;
        asm("{.reg .u64 t; cvta.to.shared.u64 t, %1; cvt.u32.u64 %0, t;}"
            : "=r"(sb) : "l"(sh));

        int re[5], ce[5];
        #pragma unroll
        for (int j = 0; j < 5; j++) { int idx = tid + j * 640; re[j] = idx / 200; ce[j] = idx % 200; }
        const int ri0 = tid / 50,          ci0 = tid % 50;
        const int ri1 = (tid + 640) / 50,  ci1 = (tid + 640) % 50;
        const bool has_i1 = (tid < 160);

        auto issue = [&](int buf, int tile) {
            if (tile >= AGG_TILES) return;
            int t0 = tile * AGG_T;
            unsigned she = sb + buf * (BUF_FLOATS * 4);
            unsigned shi = she + AGG_T * EPAD * 4;
            #pragma unroll
            for (int j = 0; j < 5; j++)
                cp16(she + (re[j] * EPAD + 4 * ce[j]) * 4,
                     S_e + (size_t)(t0 + re[j]) * E_NO + 4 * ce[j]);
            cp16(shi + (ri0 * IPAD + 4 * ci0) * 4,
                 S_i + (size_t)(t0 + ri0) * I_NO + 4 * ci0);
            if (has_i1)
                cp16(shi + (ri1 * IPAD + 4 * ci1) * 4,
                     S_i + (size_t)(t0 + ri1) * I_NO + 4 * ci1);
        };

        int tile = bid;
        issue(0, tile);
        asm volatile("cp.async.commit_group;");
        issue(1, tile + NAGG);
        asm volatile("cp.async.commit_group;");

        int p = 0;
        for (; tile < AGG_TILES; tile += NAGG) {
            asm volatile("cp.async.wait_group 1;");
            __syncthreads();
            const float* bufe = sh + p * BUF_FLOATS;
            const float* bufi = bufe + AGG_T * EPAD;
            const int t0 = tile * AGG_T;
            {
                const float* row = bufe + lr * EPAD;
                float a0 = 0.f, a1 = 0.f;
                int j = be + (l >> 4);
                for (; j + 2 < ee; j += 4) { a0 += row[s_el[j]]; a1 += row[s_el[j + 2]]; }
                if (j < ee) a0 += row[s_el[j]];
                float a = a0 + a1;
                a += __shfl_down_sync(0xffffffffu, a, 16);
                if (l < 16) g_syn_e[w * T_DATA + t0 + lr] = a;
            }
            {
                const float* row = bufi + lr * IPAD;
                float a0 = 0.f, a1 = 0.f;
                int j = bi + (l >> 4);
                for (; j + 2 < ei; j += 4) { a0 += row[s_il[j]]; a1 += row[s_il[j + 2]]; }
                if (j < ei) a0 += row[s_il[j]];
                float a = a0 + a1;
                a += __shfl_down_sync(0xffffffffu, a, 16);
                if (l < 16) g_syn_i[w * T_DATA + t0 + lr] = a;
            }
            // publish tile: syncthreads (CTA happens-before) + one release-red.
            // NO __threadfence here: CCTL.IVALL would hit in-flight LDGSTS.
            __syncthreads();
            if (tid == 0) red_release_add(&g_cnt[tile / SEG_TILES], 1u);
            issue((p + 2) % NBUF, tile + 2 * NAGG);
            asm volatile("cp.async.commit_group;");
            p = (p + 1) % NBUF;
        }
        asm volatile("cp.async.wait_group 0;");   // drain before smem reuse
        __syncthreads();
    }

    // ---------------- phase B: fir job consumption (all blocks) -----------
    {
        float* win = sh;                 // F_WIN floats
        float* fkd = sh + F_WIN;         // 2*FKP duplicated taps
        for (;;) {
            __syncthreads();             // protect smem reuse across jobs
            if (tid == 0) sjob = (int)atomicAdd(&g_job, 1u);
            __syncthreads();
            int job = sjob;
            if (job >= NJOB) break;
            int seg = job / (2 * SUB_NO);
            int cs  = job % (2 * SUB_NO);
            int ch  = cs / SUB_NO, s = cs % SUB_NO;
            const float* src = ch ? g_syn_i : g_syn_e;
            float*       dst = ch ? g_fir_i : g_fir_e;
            const int t0 = seg * F_T;

            if (tid == 0) {              // acquire-spin on segment readiness
                unsigned need = (seg < NSEG - 1) ? SEG_TILES
                                                 : (AGG_TILES - (NSEG - 1) * SEG_TILES);
                while (ld_acquire(&g_cnt[seg]) < need) { }
                if (seg > 0)
                    while (ld_acquire(&g_cnt[seg - 1]) < SEG_TILES) { }
            }
            __syncthreads();

            for (int q = tid; q < 2 * FKP / 4; q += THREADS)
                ((float4*)fkd)[q] = ((const float4*)&g_fk2[(ch * SUB_NO + s) * 2 * FKP])[q];
            // stage window with L2-only loads (__ldcg): no stale-L1 exposure
            for (int r = tid; r < F_WIN / 4; r += THREADS) {
                int tb = t0 - 200 + 4 * r;
                float4 v;
                if (tb >= 0 && tb + 3 < T_DATA) {
                    v = __ldcg((const float4*)&src[s * T_DATA + tb]);
                } else {
                    float x[4];
                    #pragma unroll
                    for (int k = 0; k < 4; k++) {
                        int t = tb + k;
                        x[k] = (t >= 0 && t < T_DATA) ? __ldcg(&src[s * T_DATA + t]) : 0.f;
                    }
                    v = make_float4(x[0], x[1], x[2], x[3]);
                }
                *(float4*)&win[4 * r] = v;
            }
            __syncthreads();

            u64 A0 = 0, A1 = 0, A2 = 0, A3 = 0, A4 = 0, A5 = 0, A6 = 0, A7 = 0;
            const float* wp = &win[16 * tid];
            {
                float4 v0 = *(const float4*)&wp[0];
                float4 v1 = *(const float4*)&wp[4];
                float4 v2 = *(const float4*)&wp[8];
                float4 v3 = *(const float4*)&wp[12];
                float4 v4 = *(const float4*)&wp[16];
                u64 P0  = pk2(v0.x, v2.x), P1  = pk2(v0.y, v2.y);
                u64 P2  = pk2(v0.z, v2.z), P3  = pk2(v0.w, v2.w);
                u64 P4  = pk2(v1.x, v3.x), P5  = pk2(v1.y, v3.y);
                u64 P6  = pk2(v1.z, v3.z), P7  = pk2(v1.w, v3.w);
                u64 P8  = pk2(v2.x, v4.x), P9  = pk2(v2.y, v4.y);
                u64 P10 = pk2(v2.z, v4.z), P11 = pk2(v2.w, v4.w);
                #pragma unroll 17
                for (int g = 0; g < NGROUP - 1; g++) {
                    const ulonglong2* kd = (const ulonglong2*)&fkd[8 * g];
                    ulonglong2 k01 = kd[0];
                    ulonglong2 k23 = kd[1];
                    ffma2(A0, k01.x, P0); ffma2(A1, k01.x, P1);
                    ffma2(A2, k01.x, P2); ffma2(A3, k01.x, P3);
                    ffma2(A4, k01.x, P4); ffma2(A5, k01.x, P5);
                    ffma2(A6, k01.x, P6); ffma2(A7, k01.x, P7);
                    ffma2(A0, k01.y, P1); ffma2(A1, k01.y, P2);
                    ffma2(A2, k01.y, P3); ffma2(A3, k01.y, P4);
                    ffma2(A4, k01.y, P5); ffma2(A5, k01.y, P6);
                    ffma2(A6, k01.y, P7); ffma2(A7, k01.y, P8);
                    ffma2(A0, k23.x, P2); ffma2(A1, k23.x, P3);
                    ffma2(A2, k23.x, P4); ffma2(A3, k23.x, P5);
                    ffma2(A4, k23.x, P6); ffma2(A5, k23.x, P7);
                    ffma2(A6, k23.x, P8); ffma2(A7, k23.x, P9);
                    ffma2(A0, k23.y, P3); ffma2(A1, k23.y, P4);
                    ffma2(A2, k23.y, P5); ffma2(A3, k23.y, P6);
                    ffma2(A4, k23.y, P7); ffma2(A5, k23.y, P8);
                    ffma2(A6, k23.y, P9); ffma2(A7, k23.y, P10);
                    float4 nv = *(const float4*)&wp[4 * g + 20];
                    float d0, h4, h5, h6, h7;
                    upk2(P4, d0, h4); upk2(P5, d0, h5);
                    upk2(P6, d0, h6); upk2(P7, d0, h7);
                    P0 = P4;  P1 = P5;  P2 = P6;  P3 = P7;
                    P4 = P8;  P5 = P9;  P6 = P10; P7 = P11;
                    P8  = pk2(h4, nv.x); P9  = pk2(h5, nv.y);
                    P10 = pk2(h6, nv.z); P11 = pk2(h7, nv.w);
                }
                {
                    const ulonglong2* kd = (const ulonglong2*)&fkd[8 * (NGROUP - 1)];
                    ulonglong2 k01 = kd[0];
                    ulonglong2 k23 = kd[1];
                    ffma2(A0, k01.x, P0); ffma2(A1, k01.x, P1);
                    ffma2(A2, k01.x, P2); ffma2(A3, k01.x, P3);
                    ffma2(A4, k01.x, P4); ffma2(A5, k01.x, P5);
                    ffma2(A6, k01.x, P6); ffma2(A7, k01.x, P7);
                    ffma2(A0, k01.y, P1); ffma2(A1, k01.y, P2);
                    ffma2(A2, k01.y, P3); ffma2(A3, k01.y, P4);
                    ffma2(A4, k01.y, P5); ffma2(A5, k01.y, P6);
                    ffma2(A6, k01.y, P7); ffma2(A7, k01.y, P8);
                    ffma2(A0, k23.x, P2); ffma2(A1, k23.x, P3);
                    ffma2(A2, k23.x, P4); ffma2(A3, k23.x, P5);
                    ffma2(A4, k23.x, P6); ffma2(A5, k23.x, P7);
                    ffma2(A6, k23.x, P8); ffma2(A7, k23.x, P9);
                    ffma2(A0, k23.y, P3); ffma2(A1, k23.y, P4);
                    ffma2(A2, k23.y, P5); ffma2(A3, k23.y, P6);
                    ffma2(A4, k23.y, P7); ffma2(A5, k23.y, P8);
                    ffma2(A6, k23.y, P9); ffma2(A7, k23.y, P10);
                }
            }
            float lo0, lo1, lo2, lo3, lo4, lo5, lo6, lo7;
            float hi0, hi1, hi2, hi3, hi4, hi5, hi6, hi7;
            upk2(A0, lo0, hi0); upk2(A1, lo1, hi1);
            upk2(A2, lo2, hi2); upk2(A3, lo3, hi3);
            upk2(A4, lo4, hi4); upk2(A5, lo5, hi5);
            upk2(A6, lo6, hi6); upk2(A7, lo7, hi7);

            int t = t0 + 16 * tid;
            if (t + 15 < T_DATA) {
                *(float4*)&dst[s * T_DATA + t]      = make_float4(lo0, lo1, lo2, lo3);
                *(float4*)&dst[s * T_DATA + t + 4]  = make_float4(lo4, lo5, lo6, lo7);
                *(float4*)&dst[s * T_DATA + t + 8]  = make_float4(hi0, hi1, hi2, hi3);
                *(float4*)&dst[s * T_DATA + t + 12] = make_float4(hi4, hi5, hi6, hi7);
            } else {
                float a[16] = {lo0, lo1, lo2, lo3, lo4, lo5, lo6, lo7,
                               hi0, hi1, hi2, hi3, hi4, hi5, hi6, hi7};
                #pragma unroll
                for (int k = 0; k < 16; k++)
                    if (t + k < T_DATA) dst[s * T_DATA + t + k] = a[k];
            }
        }
    }

    // ---------------- grid barrier (release/acquire, no L1 flush) ---------
    __syncthreads();
    if (tid == 0) {
        unsigned sense = ld_acquire(&g_bar_sense);
        if (atom_add_release(&g_bar_cnt, 1u) == GRID - 1) {
            g_bar_cnt = 0;                        // all arrived; plain store ok
            atom_add_release(&g_bar_sense, 1u);   // orders the reset before it
        } else {
            while (ld_acquire(&g_bar_sense) == sense) { }
        }
    }
    __syncthreads();

    // reset ticket/counters for next launch (no block reads them post-barrier)
    if (bid == 0 && tid == 0) {
        g_job = 0;
        #pragma unroll
        for (int k = 0; k < NSEG; k++) g_cnt[k] = 0;
    }

    // ---------------- phase C: tree recursion + C_syn copies --------------
    for (int q = bid * THREADS + tid; q < SUB_NO * (E_NO + I_NO); q += GRID * THREADS) {
        if (q < SUB_NO * E_NO)
            out_v[T_DATA + 2 * SUB_NO * T_NO + q] = Cse[q];
        else
            out_v[T_DATA + 2 * SUB_NO * T_NO + q] = Csi[q - SUB_NO * E_NO];
    }
    for (int idx = tid; idx < SUB_NO * SUB_NO; idx += THREADS) {
        int c = idx % SUB_NO;
        cw[idx] = C_den[idx] * expf(W_sub[c]);
    }
    if (tid < SUB_NO) th[tid] = Theta[tid];
    __syncthreads();

    const float wexp0 = expf(W_sub[0]);
    const float vo    = V_o[0];
    for (int t = bid * THREADS + tid; t < T_DATA; t += GRID * THREADS) {
        float f[SUB_NO];
        #pragma unroll
        for (int s = 0; s < SUB_NO; s++)
            f[s] = __ldcg(&g_fir_e[s * T_DATA + t]) + __ldcg(&g_fir_i[s * T_DATA + t]);
        float sub[SUB_NO];
        #pragma unroll
        for (int s = 0; s < SUB_NO; s++) sub[s] = 0.f;
        #pragma unroll
        for (int s = SUB_NO - 1; s >= 0; s--) {
            float leaf = 0.f;
            #pragma unroll
            for (int c = s + 1; c < SUB_NO; c++)
                leaf = fmaf(cw[s * SUB_NO + c], sub[c], leaf);
            sub[s] = tanhf(f[s] + leaf + th[s]);
        }
        out_v[t] = sub[0] * wexp0 + vo;
    }
}

// ============================= launch ======================================
extern "C" void kernel_launch(void* const* d_in, const int* in_sizes, int n_in,
                              void* d_out, int out_size) {
    const float* S_e   = (const float*)d_in[0];
    const float* S_i   = (const float*)d_in[1];
    const float* Cse   = (const float*)d_in[2];
    const float* Csi   = (const float*)d_in[3];
    const float* Cden  = (const float*)d_in[4];
    const float* Wsyn  = (const float*)d_in[5];
    const float* Tau   = (const float*)d_in[6];
    const float* Delta = (const float*)d_in[7];
    const float* Wsub  = (const float*)d_in[8];
    const float* Theta = (const float*)d_in[9];
    const float* Vo    = (const float*)d_in[10];
    float* out = (float*)d_out;

    cudaFuncSetAttribute(k_main, cudaFuncAttributeMaxDynamicSharedMemorySize, DYN_SMEM);

    // output layout: [0,100000) voltage | [100000,108040) filters |
    // [108040,124040) C_syn_e | [124040,128040) C_syn_i
    k_setup<<<1, 512>>>(Cse, Csi, Wsyn, Tau, Delta, out + T_DATA);
    k_main<<<GRID, THREADS, DYN_SMEM>>>(S_e, S_i, Cden, Wsub, Theta, Vo,
                                        Cse, Csi, out);
}

// round 15
// speedup vs baseline: 1.9670x; 1.9670x over previous
#include <cuda_runtime.h>
#include <math.h>

#define SUB_NO 20
#define T_NO   201
#define T_DATA 100000
#define E_NO   800
#define I_NO   200

#define FKP     208            // flipped kernel row, padded (zeros at 201..207)
#define NGROUP  52             // FKP/4 tap groups

#define AGG_T     16           // t rows per tile
#define AGG_TILES (T_DATA / AGG_T)   // 6250
#define AGG_GRID  296          // ~2 waves at 1 block/SM
#define EPAD 804               // e-row stride (16B-aligned)
#define IPAD 204               // i-row stride
#define BUF_FLOATS (AGG_T * EPAD + AGG_T * IPAD)   // 16128
#define NBUF 3

#define FIR_T    2048          // outputs per fir block
#define FIR_THREADS 128        // 16 outputs/thread
#define FIR_WIN  2264          // 2048 + 200 halo + pad (566 float4)
#define FIR_CHUNKS ((T_DATA + FIR_T - 1) / FIR_T)   // 49

#define TREE_THREADS 256

#define AGG_SMEM  ((NBUF * BUF_FLOATS + E_NO + I_NO) * 4)
#define FIR_SMEM  ((FIR_WIN + 2 * FKP) * 4)

typedef unsigned long long u64;

__device__ __forceinline__ u64 pk2(float lo, float hi) {
    u64 r; asm("mov.b64 %0, {%1, %2};" : "=l"(r) : "f"(lo), "f"(hi)); return r;
}
__device__ __forceinline__ void upk2(u64 p, float& lo, float& hi) {
    asm("mov.b64 {%0, %1}, %2;" : "=f"(lo), "=f"(hi) : "l"(p));
}
// packed dual fp32 fma: d = a*b + d  (SASS FFMA2)
__device__ __forceinline__ void ffma2(u64& d, u64 a, u64 b) {
    asm("fma.rn.f32x2 %0, %1, %2, %0;" : "+l"(d) : "l"(a), "l"(b));
}
// 16B async global->shared copy (LDGSTS)
__device__ __forceinline__ void cp16(unsigned dst, const float* src) {
    asm volatile("cp.async.cg.shared.global [%0], [%1], 16;" :: "r"(dst), "l"(src));
}

// -------- device scratch (no allocations allowed) --------
__device__ float g_syn_e[SUB_NO * T_DATA];
__device__ float g_syn_i[SUB_NO * T_DATA];
__device__ float g_fir_e[SUB_NO * T_DATA];
__device__ float g_fir_i[SUB_NO * T_DATA];
__device__ float g_fk2[2 * SUB_NO * 2 * FKP];    // flipped taps, duplicated (k,k)
__device__ int   g_elist[E_NO];
__device__ int   g_ilist[I_NO];
__device__ int   g_eoff[SUB_NO + 1];
__device__ int   g_ioff[SUB_NO + 1];

// ================= K0: setup (lists, alpha kernels, filters out) ===========
__global__ void __launch_bounds__(512)
k_setup(const float* __restrict__ Cse, const float* __restrict__ Csi,
        const float* __restrict__ Wsyn, const float* __restrict__ Tau,
        const float* __restrict__ Delta,
        float* __restrict__ out_filters) {
    __shared__ int s_ae[E_NO];
    __shared__ int s_ai[I_NO];
    __shared__ int s_cnt_e[SUB_NO], s_cnt_i[SUB_NO];
    __shared__ int s_off_e[SUB_NO + 1], s_off_i[SUB_NO + 1];
    const int tid = threadIdx.x;

    // ---- alpha kernels ----
    for (int idx = tid; idx < 2 * SUB_NO * T_NO; idx += blockDim.x) {
        int t  = idx % T_NO;
        int sc = idx / T_NO;          // row of vstack: c*20 + s
        int c  = sc / SUB_NO;
        int s  = sc % SUB_NO;
        float v = 0.f;
        #pragma unroll
        for (int j = 0; j < 2; j++) {
            float W   = Wsyn [(s * 2 + j) * 2 + c];
            float tau = Tau  [(s * 2 + j) * 2 + c];
            float dl  = Delta[(s * 2 + j) * 2 + c];
            float td  = fmaxf((float)t - dl, 0.f);
            float tt  = td * expf(-tau);
            v += tt * expf(-tt) * W;
        }
        out_filters[sc * T_NO + t] = v;
        int u = T_NO - 1 - t;                 // flipped
        g_fk2[sc * 2 * FKP + 2 * u]     = v;
        g_fk2[sc * 2 * FKP + 2 * u + 1] = v;
    }
    for (int idx = tid; idx < 2 * SUB_NO * (FKP - T_NO); idx += blockDim.x) {
        int sc = idx / (FKP - T_NO);
        int p  = idx % (FKP - T_NO);
        int u  = T_NO + p;
        g_fk2[sc * 2 * FKP + 2 * u]     = 0.f;
        g_fk2[sc * 2 * FKP + 2 * u + 1] = 0.f;
    }

    // ---- assignments + counts ----
    if (tid < SUB_NO) { s_cnt_e[tid] = 0; s_cnt_i[tid] = 0; }
    __syncthreads();
    for (int e = tid; e < E_NO; e += blockDim.x) {
        int a = 0;
        #pragma unroll
        for (int s = 0; s < SUB_NO; s++) a += s * (Cse[s * E_NO + e] > 0.5f);
        s_ae[e] = a;
        atomicAdd(&s_cnt_e[a], 1);
    }
    for (int i = tid; i < I_NO; i += blockDim.x) {
        int a = 0;
        #pragma unroll
        for (int s = 0; s < SUB_NO; s++) a += s * (Csi[s * I_NO + i] > 0.5f);
        s_ai[i] = a;
        atomicAdd(&s_cnt_i[a], 1);
    }
    __syncthreads();
    if (tid == 0) {
        int acc = 0;
        for (int s = 0; s < SUB_NO; s++) { s_off_e[s] = acc; acc += s_cnt_e[s]; }
        s_off_e[SUB_NO] = acc;
        acc = 0;
        for (int s = 0; s < SUB_NO; s++) { s_off_i[s] = acc; acc += s_cnt_i[s]; }
        s_off_i[SUB_NO] = acc;
    }
    __syncthreads();
    // ---- deterministic parallel scatter via rank ----
    for (int e = tid; e < E_NO; e += blockDim.x) {
        int a = s_ae[e], r = 0;
        for (int p = 0; p < e; p++) r += (s_ae[p] == a);
        g_elist[s_off_e[a] + r] = e;
    }
    for (int i = tid; i < I_NO; i += blockDim.x) {
        int a = s_ai[i], r = 0;
        for (int p = 0; p < i; p++) r += (s_ai[p] == a);
        g_ilist[s_off_i[a] + r] = i;
    }
    if (tid <= SUB_NO) { g_eoff[tid] = s_off_e[tid]; g_ioff[tid] = s_off_i[tid]; }
}

// ================= K1: persistent triple-buffered cp.async aggregation ====
__global__ void __launch_bounds__(640, 1)
k_agg(const float* __restrict__ S_e, const float* __restrict__ S_i) {
    extern __shared__ float sh[];
    int* s_el = (int*)(sh + NBUF * BUF_FLOATS);
    int* s_il = s_el + E_NO;
    const int tid = threadIdx.x;
    const int w   = tid >> 5;            // warp = subunit
    const int l   = tid & 31;
    const int lr  = l & 15;              // row within tile

    for (int q = tid; q < E_NO; q += 640) s_el[q] = g_elist[q];
    for (int q = tid; q < I_NO; q += 640) s_il[q] = g_ilist[q];
    const int be = g_eoff[w], ee = g_eoff[w + 1];
    const int bi = g_ioff[w], ei = g_ioff[w + 1];

    unsigned sb;
    asm("{.reg .u64 t; cvta.to.shared.u64 t, %1; cvt.u32.u64 %0, t;}"
        : "=r"(sb) : "l"(sh));

    int re[5], ce[5];
    #pragma unroll
    for (int j = 0; j < 5; j++) { int idx = tid + j * 640; re[j] = idx / 200; ce[j] = idx % 200; }
    const int ri0 = tid / 50,          ci0 = tid % 50;
    const int ri1 = (tid + 640) / 50,  ci1 = (tid + 640) % 50;
    const bool has_i1 = (tid < 160);

    auto issue = [&](int buf, int tile) {
        if (tile >= AGG_TILES) return;
        int t0 = tile * AGG_T;
        unsigned she = sb + buf * (BUF_FLOATS * 4);
        unsigned shi = she + AGG_T * EPAD * 4;
        #pragma unroll
        for (int j = 0; j < 5; j++)
            cp16(she + (re[j] * EPAD + 4 * ce[j]) * 4,
                 S_e + (size_t)(t0 + re[j]) * E_NO + 4 * ce[j]);
        cp16(shi + (ri0 * IPAD + 4 * ci0) * 4,
             S_i + (size_t)(t0 + ri0) * I_NO + 4 * ci0);
        if (has_i1)
            cp16(shi + (ri1 * IPAD + 4 * ci1) * 4,
                 S_i + (size_t)(t0 + ri1) * I_NO + 4 * ci1);
    };

    int tile = blockIdx.x;
    issue(0, tile);
    asm volatile("cp.async.commit_group;");
    issue(1, tile + AGG_GRID);
    asm volatile("cp.async.commit_group;");

    int p = 0;
    for (; tile < AGG_TILES; tile += AGG_GRID) {
        asm volatile("cp.async.wait_group 1;");
        __syncthreads();
        const float* bufe = sh + p * BUF_FLOATS;
        const float* bufi = bufe + AGG_T * EPAD;
        const int t0 = tile * AGG_T;
        {   // e-gather (half-warp split even/odd list entries)
            const float* row = bufe + lr * EPAD;
            float a0 = 0.f, a1 = 0.f;
            int j = be + (l >> 4);
            for (; j + 2 < ee; j += 4) { a0 += row[s_el[j]]; a1 += row[s_el[j + 2]]; }
            if (j < ee) a0 += row[s_el[j]];
            float a = a0 + a1;
            a += __shfl_down_sync(0xffffffffu, a, 16);
            if (l < 16) g_syn_e[w * T_DATA + t0 + lr] = a;
        }
        {   // i-gather
            const float* row = bufi + lr * IPAD;
            float a0 = 0.f, a1 = 0.f;
            int j = bi + (l >> 4);
            for (; j + 2 < ei; j += 4) { a0 += row[s_il[j]]; a1 += row[s_il[j + 2]]; }
            if (j < ei) a0 += row[s_il[j]];
            float a = a0 + a1;
            a += __shfl_down_sync(0xffffffffu, a, 16);
            if (l < 16) g_syn_i[w * T_DATA + t0 + lr] = a;
        }
        issue((p + 2) % NBUF, tile + 2 * AGG_GRID);
        asm volatile("cp.async.commit_group;");
        p = (p + 1) % NBUF;
    }
    asm volatile("cp.async.wait_group 0;");
}

// ================= K2: grouped causal FIR, 16 outputs/thread ==============
// Accumulator pairs at output-stride 8: A_p = (out_p, out_{p+8}); window
// packs P_j = (b_j, b_{j+8}), 12 live. Per 4-tap group: 32 FFMA2 + 3 LDS +
// slide -> ~0.8 issue slots per MAC.
__global__ void __launch_bounds__(FIR_THREADS)
k_fir(void) {
    extern __shared__ float sh[];
    float* win = sh;                   // FIR_WIN
    float* fkd = win + FIR_WIN;        // 2*FKP duplicated taps

    const int bid   = blockIdx.x;
    const int s     = bid % SUB_NO;
    const int chunk = (bid / SUB_NO) % FIR_CHUNKS;
    const int ch    = bid / (SUB_NO * FIR_CHUNKS);
    const int t0    = chunk * FIR_T;
    const int tid   = threadIdx.x;

    const float* src = ch ? g_syn_i : g_syn_e;
    float*       dst = ch ? g_fir_i : g_fir_e;

    // stage duplicated filters for this (ch, s)
    for (int q = tid; q < 2 * FKP / 4; q += FIR_THREADS)
        ((float4*)fkd)[q] = ((const float4*)&g_fk2[(ch * SUB_NO + s) * 2 * FKP])[q];

    // stage window: win[j] = src[s][t0-200+j], 0 outside [0,T_DATA)
    for (int r = tid; r < FIR_WIN / 4; r += FIR_THREADS) {
        int tb = t0 - 200 + 4 * r;       // multiple of 4
        float4 v;
        if (tb >= 0 && tb + 3 < T_DATA) {
            v = *(const float4*)&src[s * T_DATA + tb];
        } else {
            float x[4];
            #pragma unroll
            for (int k = 0; k < 4; k++) {
                int t = tb + k;
                x[k] = (t >= 0 && t < T_DATA) ? src[s * T_DATA + t] : 0.f;
            }
            v = make_float4(x[0], x[1], x[2], x[3]);
        }
        *(float4*)&win[4 * r] = v;
    }
    __syncthreads();

    u64 A0 = 0, A1 = 0, A2 = 0, A3 = 0, A4 = 0, A5 = 0, A6 = 0, A7 = 0;
    const float* wp = &win[16 * tid];
    {
        float4 v0 = *(const float4*)&wp[0];
        float4 v1 = *(const float4*)&wp[4];
        float4 v2 = *(const float4*)&wp[8];
        float4 v3 = *(const float4*)&wp[12];
        float4 v4 = *(const float4*)&wp[16];
        u64 P0  = pk2(v0.x, v2.x), P1  = pk2(v0.y, v2.y);
        u64 P2  = pk2(v0.z, v2.z), P3  = pk2(v0.w, v2.w);
        u64 P4  = pk2(v1.x, v3.x), P5  = pk2(v1.y, v3.y);
        u64 P6  = pk2(v1.z, v3.z), P7  = pk2(v1.w, v3.w);
        u64 P8  = pk2(v2.x, v4.x), P9  = pk2(v2.y, v4.y);
        u64 P10 = pk2(v2.z, v4.z), P11 = pk2(v2.w, v4.w);
        #pragma unroll 17
        for (int g = 0; g < NGROUP - 1; g++) {       // 51 groups with slide
            const ulonglong2* kd = (const ulonglong2*)&fkd[8 * g];
            ulonglong2 k01 = kd[0];      // (tap0,tap0) (tap1,tap1)
            ulonglong2 k23 = kd[1];      // (tap2,tap2) (tap3,tap3)
            ffma2(A0, k01.x, P0); ffma2(A1, k01.x, P1);
            ffma2(A2, k01.x, P2); ffma2(A3, k01.x, P3);
            ffma2(A4, k01.x, P4); ffma2(A5, k01.x, P5);
            ffma2(A6, k01.x, P6); ffma2(A7, k01.x, P7);
            ffma2(A0, k01.y, P1); ffma2(A1, k01.y, P2);
            ffma2(A2, k01.y, P3); ffma2(A3, k01.y, P4);
            ffma2(A4, k01.y, P5); ffma2(A5, k01.y, P6);
            ffma2(A6, k01.y, P7); ffma2(A7, k01.y, P8);
            ffma2(A0, k23.x, P2); ffma2(A1, k23.x, P3);
            ffma2(A2, k23.x, P4); ffma2(A3, k23.x, P5);
            ffma2(A4, k23.x, P6); ffma2(A5, k23.x, P7);
            ffma2(A6, k23.x, P8); ffma2(A7, k23.x, P9);
            ffma2(A0, k23.y, P3); ffma2(A1, k23.y, P4);
            ffma2(A2, k23.y, P5); ffma2(A3, k23.y, P6);
            ffma2(A4, k23.y, P7); ffma2(A5, k23.y, P8);
            ffma2(A6, k23.y, P9); ffma2(A7, k23.y, P10);
            // slide window by 4 taps
            float4 nv = *(const float4*)&wp[4 * g + 20];
            float d0, h4, h5, h6, h7;
            upk2(P4, d0, h4); upk2(P5, d0, h5);
            upk2(P6, d0, h6); upk2(P7, d0, h7);
            P0 = P4;  P1 = P5;  P2 = P6;  P3 = P7;
            P4 = P8;  P5 = P9;  P6 = P10; P7 = P11;
            P8  = pk2(h4, nv.x); P9  = pk2(h5, nv.y);
            P10 = pk2(h6, nv.z); P11 = pk2(h7, nv.w);
        }
        {   // last group (taps 204..207 are zero beyond 200; no slide)
            const ulonglong2* kd = (const ulonglong2*)&fkd[8 * (NGROUP - 1)];
            ulonglong2 k01 = kd[0];
            ulonglong2 k23 = kd[1];
            ffma2(A0, k01.x, P0); ffma2(A1, k01.x, P1);
            ffma2(A2, k01.x, P2); ffma2(A3, k01.x, P3);
            ffma2(A4, k01.x, P4); ffma2(A5, k01.x, P5);
            ffma2(A6, k01.x, P6); ffma2(A7, k01.x, P7);
            ffma2(A0, k01.y, P1); ffma2(A1, k01.y, P2);
            ffma2(A2, k01.y, P3); ffma2(A3, k01.y, P4);
            ffma2(A4, k01.y, P5); ffma2(A5, k01.y, P6);
            ffma2(A6, k01.y, P7); ffma2(A7, k01.y, P8);
            ffma2(A0, k23.x, P2); ffma2(A1, k23.x, P3);
            ffma2(A2, k23.x, P4); ffma2(A3, k23.x, P5);
            ffma2(A4, k23.x, P6); ffma2(A5, k23.x, P7);
            ffma2(A6, k23.x, P8); ffma2(A7, k23.x, P9);
            ffma2(A0, k23.y, P3); ffma2(A1, k23.y, P4);
            ffma2(A2, k23.y, P5); ffma2(A3, k23.y, P6);
            ffma2(A4, k23.y, P7); ffma2(A5, k23.y, P8);
            ffma2(A6, k23.y, P9); ffma2(A7, k23.y, P10);
        }
    }
    float lo0, lo1, lo2, lo3, lo4, lo5, lo6, lo7;
    float hi0, hi1, hi2, hi3, hi4, hi5, hi6, hi7;
    upk2(A0, lo0, hi0); upk2(A1, lo1, hi1);
    upk2(A2, lo2, hi2); upk2(A3, lo3, hi3);
    upk2(A4, lo4, hi4); upk2(A5, lo5, hi5);
    upk2(A6, lo6, hi6); upk2(A7, lo7, hi7);

    int t = t0 + 16 * tid;
    if (t + 15 < T_DATA) {
        *(float4*)&dst[s * T_DATA + t]      = make_float4(lo0, lo1, lo2, lo3);
        *(float4*)&dst[s * T_DATA + t + 4]  = make_float4(lo4, lo5, lo6, lo7);
        *(float4*)&dst[s * T_DATA + t + 8]  = make_float4(hi0, hi1, hi2, hi3);
        *(float4*)&dst[s * T_DATA + t + 12] = make_float4(hi4, hi5, hi6, hi7);
    } else {
        float a[16] = {lo0, lo1, lo2, lo3, lo4, lo5, lo6, lo7,
                       hi0, hi1, hi2, hi3, hi4, hi5, hi6, hi7};
        #pragma unroll
        for (int k = 0; k < 16; k++)
            if (t + k < T_DATA) dst[s * T_DATA + t + k] = a[k];
    }
}

// ================= K3: dendritic tree recursion (1 t per thread) ==========
__global__ void __launch_bounds__(TREE_THREADS)
k_tree(const float* __restrict__ C_den, const float* __restrict__ W_sub,
       const float* __restrict__ Theta, const float* __restrict__ V_o,
       const float* __restrict__ Cse, const float* __restrict__ Csi,
       float* __restrict__ out_v) {
    __shared__ float cw[SUB_NO * SUB_NO];
    __shared__ float th[SUB_NO];
    const int tid  = threadIdx.x;
    const int gidx = blockIdx.x * TREE_THREADS + tid;

    // fold the C_syn copies into this kernel (grid covers 100096 >= 20000)
    if (gidx < SUB_NO * E_NO) {
        out_v[T_DATA + 2 * SUB_NO * T_NO + gidx] = Cse[gidx];
    } else if (gidx < SUB_NO * E_NO + SUB_NO * I_NO) {
        int q = gidx - SUB_NO * E_NO;
        out_v[T_DATA + 2 * SUB_NO * T_NO + SUB_NO * E_NO + q] = Csi[q];
    }

    for (int idx = tid; idx < SUB_NO * SUB_NO; idx += TREE_THREADS) {
        int c = idx % SUB_NO;
        cw[idx] = C_den[idx] * expf(W_sub[c]);
    }
    if (tid < SUB_NO) th[tid] = Theta[tid];
    __syncthreads();

    const int t = gidx;
    if (t >= T_DATA) return;

    float f[SUB_NO];
    #pragma unroll
    for (int s = 0; s < SUB_NO; s++)
        f[s] = g_fir_e[s * T_DATA + t] + g_fir_i[s * T_DATA + t];

    float sub[SUB_NO];
    #pragma unroll
    for (int s = 0; s < SUB_NO; s++) sub[s] = 0.f;
    #pragma unroll
    for (int s = SUB_NO - 1; s >= 0; s--) {
        float leaf = 0.f;
        #pragma unroll
        for (int c = s + 1; c < SUB_NO; c++)
            leaf = fmaf(cw[s * SUB_NO + c], sub[c], leaf);
        sub[s] = tanhf(f[s] + leaf + th[s]);
    }
    out_v[t] = sub[0] * expf(W_sub[0]) + V_o[0];
}

// ============================= launch ======================================
extern "C" void kernel_launch(void* const* d_in, const int* in_sizes, int n_in,
                              void* d_out, int out_size) {
    const float* S_e   = (const float*)d_in[0];
    const float* S_i   = (const float*)d_in[1];
    const float* Cse   = (const float*)d_in[2];
    const float* Csi   = (const float*)d_in[3];
    const float* Cden  = (const float*)d_in[4];
    const float* Wsyn  = (const float*)d_in[5];
    const float* Tau   = (const float*)d_in[6];
    const float* Delta = (const float*)d_in[7];
    const float* Wsub  = (const float*)d_in[8];
    const float* Theta = (const float*)d_in[9];
    const float* Vo    = (const float*)d_in[10];
    float* out = (float*)d_out;

    cudaFuncSetAttribute(k_agg, cudaFuncAttributeMaxDynamicSharedMemorySize, AGG_SMEM);
    cudaFuncSetAttribute(k_fir, cudaFuncAttributeMaxDynamicSharedMemorySize, FIR_SMEM);

    // output layout: [0,100000) voltage | [100000,108040) filters |
    // [108040,124040) C_syn_e | [124040,128040) C_syn_i
    k_setup<<<1, 512>>>(Cse, Csi, Wsyn, Tau, Delta, out + T_DATA);
    k_agg<<<AGG_GRID, 640, AGG_SMEM>>>(S_e, S_i);
    k_fir<<<2 * SUB_NO * FIR_CHUNKS, FIR_THREADS, FIR_SMEM>>>();
    k_tree<<<(T_DATA + TREE_THREADS - 1) / TREE_THREADS, TREE_THREADS>>>(
        Cden, Wsub, Theta, Vo, Cse, Csi, out);
}

// round 16
// speedup vs baseline: 2.0350x; 1.0346x over previous
#include <cuda_runtime.h>
#include <math.h>

#define SUB_NO 20
#define T_NO   201
#define T_DATA 100000
#define E_NO   800
#define I_NO   200

#define FKP     208            // flipped kernel row, padded (zeros at 201..207)
#define NGROUP  52             // FKP/4 tap groups

#define AGG_T     16           // t rows per tile
#define AGG_TILES (T_DATA / AGG_T)   // 6250
#define AGG_GRID  296          // ~2 waves at 1 block/SM
#define EPAD 804               // e-row stride (16B-aligned)
#define IPAD 204               // i-row stride
#define BUF_FLOATS (AGG_T * EPAD + AGG_T * IPAD)   // 16128
#define NBUF 3

#define FIR_T    2048          // outputs per fir block
#define FIR_THREADS 128        // 16 outputs/thread
#define FIR_WIN  2264          // 2048 + 200 halo + pad (566 float4)
#define FIR_CHUNKS ((T_DATA + FIR_T - 1) / FIR_T)   // 49

#define TREE_THREADS 128
#define T_PAIRS (T_DATA / 2)   // 50000 thread-jobs, 2 t each
#define TREE_BLOCKS ((T_PAIRS + TREE_THREADS - 1) / TREE_THREADS)   // 391

#define AGG_SMEM  ((NBUF * BUF_FLOATS + E_NO + I_NO) * 4)
#define FIR_SMEM  ((FIR_WIN + 2 * FKP) * 4)

typedef unsigned long long u64;

__device__ __forceinline__ u64 pk2(float lo, float hi) {
    u64 r; asm("mov.b64 %0, {%1, %2};" : "=l"(r) : "f"(lo), "f"(hi)); return r;
}
__device__ __forceinline__ void upk2(u64 p, float& lo, float& hi) {
    asm("mov.b64 {%0, %1}, %2;" : "=f"(lo), "=f"(hi) : "l"(p));
}
// packed dual fp32 fma: d = a*b + d  (SASS FFMA2)
__device__ __forceinline__ void ffma2(u64& d, u64 a, u64 b) {
    asm("fma.rn.f32x2 %0, %1, %2, %0;" : "+l"(d) : "l"(a), "l"(b));
}
// 16B async global->shared copy (LDGSTS)
__device__ __forceinline__ void cp16(unsigned dst, const float* src) {
    asm volatile("cp.async.cg.shared.global [%0], [%1], 16;" :: "r"(dst), "l"(src));
}

// -------- device scratch (no allocations allowed) --------
__device__ float g_syn_e[SUB_NO * T_DATA];
__device__ float g_syn_i[SUB_NO * T_DATA];
__device__ float g_fir_e[SUB_NO * T_DATA];
__device__ float g_fir_i[SUB_NO * T_DATA];
__device__ float g_fk2[2 * SUB_NO * 2 * FKP];    // flipped taps, duplicated (k,k)
__device__ int   g_elist[E_NO];
__device__ int   g_ilist[I_NO];
__device__ int   g_eoff[SUB_NO + 1];
__device__ int   g_ioff[SUB_NO + 1];

// ================= K0: setup (lists in block 0; taps split over grid) ======
__global__ void __launch_bounds__(512)
k_setup(const float* __restrict__ Cse, const float* __restrict__ Csi,
        const float* __restrict__ Wsyn, const float* __restrict__ Tau,
        const float* __restrict__ Delta,
        float* __restrict__ out_filters) {
    const int tid  = threadIdx.x;
    const int gid  = blockIdx.x * blockDim.x + tid;
    const int gstr = gridDim.x * blockDim.x;

    // ---- alpha kernels (grid-strided across all blocks) ----
    for (int idx = gid; idx < 2 * SUB_NO * T_NO; idx += gstr) {
        int t  = idx % T_NO;
        int sc = idx / T_NO;          // row of vstack: c*20 + s
        int c  = sc / SUB_NO;
        int s  = sc % SUB_NO;
        float v = 0.f;
        #pragma unroll
        for (int j = 0; j < 2; j++) {
            float W   = Wsyn [(s * 2 + j) * 2 + c];
            float tau = Tau  [(s * 2 + j) * 2 + c];
            float dl  = Delta[(s * 2 + j) * 2 + c];
            float td  = fmaxf((float)t - dl, 0.f);
            float tt  = td * expf(-tau);
            v += tt * expf(-tt) * W;
        }
        out_filters[sc * T_NO + t] = v;
        int u = T_NO - 1 - t;                 // flipped
        g_fk2[sc * 2 * FKP + 2 * u]     = v;
        g_fk2[sc * 2 * FKP + 2 * u + 1] = v;
    }
    for (int idx = gid; idx < 2 * SUB_NO * (FKP - T_NO); idx += gstr) {
        int sc = idx / (FKP - T_NO);
        int p  = idx % (FKP - T_NO);
        int u  = T_NO + p;
        g_fk2[sc * 2 * FKP + 2 * u]     = 0.f;
        g_fk2[sc * 2 * FKP + 2 * u + 1] = 0.f;
    }

    // ---- list building: block 0 only ----
    if (blockIdx.x != 0) return;
    __shared__ int s_ae[E_NO];
    __shared__ int s_ai[I_NO];
    __shared__ int s_cnt_e[SUB_NO], s_cnt_i[SUB_NO];
    __shared__ int s_off_e[SUB_NO + 1], s_off_i[SUB_NO + 1];

    if (tid < SUB_NO) { s_cnt_e[tid] = 0; s_cnt_i[tid] = 0; }
    __syncthreads();
    for (int e = tid; e < E_NO; e += blockDim.x) {
        int a = 0;
        #pragma unroll
        for (int s = 0; s < SUB_NO; s++) a += s * (Cse[s * E_NO + e] > 0.5f);
        s_ae[e] = a;
        atomicAdd(&s_cnt_e[a], 1);
    }
    for (int i = tid; i < I_NO; i += blockDim.x) {
        int a = 0;
        #pragma unroll
        for (int s = 0; s < SUB_NO; s++) a += s * (Csi[s * I_NO + i] > 0.5f);
        s_ai[i] = a;
        atomicAdd(&s_cnt_i[a], 1);
    }
    __syncthreads();
    if (tid == 0) {
        int acc = 0;
        for (int s = 0; s < SUB_NO; s++) { s_off_e[s] = acc; acc += s_cnt_e[s]; }
        s_off_e[SUB_NO] = acc;
        acc = 0;
        for (int s = 0; s < SUB_NO; s++) { s_off_i[s] = acc; acc += s_cnt_i[s]; }
        s_off_i[SUB_NO] = acc;
    }
    __syncthreads();
    // deterministic parallel scatter via rank
    for (int e = tid; e < E_NO; e += blockDim.x) {
        int a = s_ae[e], r = 0;
        for (int p = 0; p < e; p++) r += (s_ae[p] == a);
        g_elist[s_off_e[a] + r] = e;
    }
    for (int i = tid; i < I_NO; i += blockDim.x) {
        int a = s_ai[i], r = 0;
        for (int p = 0; p < i; p++) r += (s_ai[p] == a);
        g_ilist[s_off_i[a] + r] = i;
    }
    if (tid <= SUB_NO) { g_eoff[tid] = s_off_e[tid]; g_ioff[tid] = s_off_i[tid]; }
}

// ================= K1: persistent triple-buffered cp.async aggregation ====
__global__ void __launch_bounds__(640, 1)
k_agg(const float* __restrict__ S_e, const float* __restrict__ S_i) {
    extern __shared__ float sh[];
    int* s_el = (int*)(sh + NBUF * BUF_FLOATS);
    int* s_il = s_el + E_NO;
    const int tid = threadIdx.x;
    const int w   = tid >> 5;            // warp = subunit
    const int l   = tid & 31;
    const int lr  = l & 15;              // row within tile

    for (int q = tid; q < E_NO; q += 640) s_el[q] = g_elist[q];
    for (int q = tid; q < I_NO; q += 640) s_il[q] = g_ilist[q];
    const int be = g_eoff[w], ee = g_eoff[w + 1];
    const int bi = g_ioff[w], ei = g_ioff[w + 1];

    unsigned sb;
    asm("{.reg .u64 t; cvta.to.shared.u64 t, %1; cvt.u32.u64 %0, t;}"
        : "=r"(sb) : "l"(sh));

    int re[5], ce[5];
    #pragma unroll
    for (int j = 0; j < 5; j++) { int idx = tid + j * 640; re[j] = idx / 200; ce[j] = idx % 200; }
    const int ri0 = tid / 50,          ci0 = tid % 50;
    const int ri1 = (tid + 640) / 50,  ci1 = (tid + 640) % 50;
    const bool has_i1 = (tid < 160);

    auto issue = [&](int buf, int tile) {
        if (tile >= AGG_TILES) return;
        int t0 = tile * AGG_T;
        unsigned she = sb + buf * (BUF_FLOATS * 4);
        unsigned shi = she + AGG_T * EPAD * 4;
        #pragma unroll
        for (int j = 0; j < 5; j++)
            cp16(she + (re[j] * EPAD + 4 * ce[j]) * 4,
                 S_e + (size_t)(t0 + re[j]) * E_NO + 4 * ce[j]);
        cp16(shi + (ri0 * IPAD + 4 * ci0) * 4,
             S_i + (size_t)(t0 + ri0) * I_NO + 4 * ci0);
        if (has_i1)
            cp16(shi + (ri1 * IPAD + 4 * ci1) * 4,
                 S_i + (size_t)(t0 + ri1) * I_NO + 4 * ci1);
    };

    int tile = blockIdx.x;
    issue(0, tile);
    asm volatile("cp.async.commit_group;");
    issue(1, tile + AGG_GRID);
    asm volatile("cp.async.commit_group;");

    int p = 0;
    for (; tile < AGG_TILES; tile += AGG_GRID) {
        asm volatile("cp.async.wait_group 1;");
        __syncthreads();
        const float* bufe = sh + p * BUF_FLOATS;
        const float* bufi = bufe + AGG_T * EPAD;
        const int t0 = tile * AGG_T;
        {   // e-gather (half-warp split even/odd list entries)
            const float* row = bufe + lr * EPAD;
            float a0 = 0.f, a1 = 0.f;
            int j = be + (l >> 4);
            for (; j + 2 < ee; j += 4) { a0 += row[s_el[j]]; a1 += row[s_el[j + 2]]; }
            if (j < ee) a0 += row[s_el[j]];
            float a = a0 + a1;
            a += __shfl_down_sync(0xffffffffu, a, 16);
            if (l < 16) g_syn_e[w * T_DATA + t0 + lr] = a;
        }
        {   // i-gather
            const float* row = bufi + lr * IPAD;
            float a0 = 0.f, a1 = 0.f;
            int j = bi + (l >> 4);
            for (; j + 2 < ei; j += 4) { a0 += row[s_il[j]]; a1 += row[s_il[j + 2]]; }
            if (j < ei) a0 += row[s_il[j]];
            float a = a0 + a1;
            a += __shfl_down_sync(0xffffffffu, a, 16);
            if (l < 16) g_syn_i[w * T_DATA + t0 + lr] = a;
        }
        issue((p + 2) % NBUF, tile + 2 * AGG_GRID);
        asm volatile("cp.async.commit_group;");
        p = (p + 1) % NBUF;
    }
    asm volatile("cp.async.wait_group 0;");
}

// ================= K2: grouped causal FIR, 16 outputs/thread ==============
__global__ void __launch_bounds__(FIR_THREADS)
k_fir(void) {
    extern __shared__ float sh[];
    float* win = sh;                   // FIR_WIN
    float* fkd = win + FIR_WIN;        // 2*FKP duplicated taps

    const int bid   = blockIdx.x;
    const int s     = bid % SUB_NO;
    const int chunk = (bid / SUB_NO) % FIR_CHUNKS;
    const int ch    = bid / (SUB_NO * FIR_CHUNKS);
    const int t0    = chunk * FIR_T;
    const int tid   = threadIdx.x;

    const float* src = ch ? g_syn_i : g_syn_e;
    float*       dst = ch ? g_fir_i : g_fir_e;

    // stage duplicated filters for this (ch, s)
    for (int q = tid; q < 2 * FKP / 4; q += FIR_THREADS)
        ((float4*)fkd)[q] = ((const float4*)&g_fk2[(ch * SUB_NO + s) * 2 * FKP])[q];

    // stage window: win[j] = src[s][t0-200+j], 0 outside [0,T_DATA)
    for (int r = tid; r < FIR_WIN / 4; r += FIR_THREADS) {
        int tb = t0 - 200 + 4 * r;       // multiple of 4
        float4 v;
        if (tb >= 0 && tb + 3 < T_DATA) {
            v = *(const float4*)&src[s * T_DATA + tb];
        } else {
            float x[4];
            #pragma unroll
            for (int k = 0; k < 4; k++) {
                int t = tb + k;
                x[k] = (t >= 0 && t < T_DATA) ? src[s * T_DATA + t] : 0.f;
            }
            v = make_float4(x[0], x[1], x[2], x[3]);
        }
        *(float4*)&win[4 * r] = v;
    }
    __syncthreads();

    u64 A0 = 0, A1 = 0, A2 = 0, A3 = 0, A4 = 0, A5 = 0, A6 = 0, A7 = 0;
    const float* wp = &win[16 * tid];
    {
        float4 v0 = *(const float4*)&wp[0];
        float4 v1 = *(const float4*)&wp[4];
        float4 v2 = *(const float4*)&wp[8];
        float4 v3 = *(const float4*)&wp[12];
        float4 v4 = *(const float4*)&wp[16];
        u64 P0  = pk2(v0.x, v2.x), P1  = pk2(v0.y, v2.y);
        u64 P2  = pk2(v0.z, v2.z), P3  = pk2(v0.w, v2.w);
        u64 P4  = pk2(v1.x, v3.x), P5  = pk2(v1.y, v3.y);
        u64 P6  = pk2(v1.z, v3.z), P7  = pk2(v1.w, v3.w);
        u64 P8  = pk2(v2.x, v4.x), P9  = pk2(v2.y, v4.y);
        u64 P10 = pk2(v2.z, v4.z), P11 = pk2(v2.w, v4.w);
        #pragma unroll 17
        for (int g = 0; g < NGROUP - 1; g++) {       // 51 groups with slide
            const ulonglong2* kd = (const ulonglong2*)&fkd[8 * g];
            ulonglong2 k01 = kd[0];      // (tap0,tap0) (tap1,tap1)
            ulonglong2 k23 = kd[1];      // (tap2,tap2) (tap3,tap3)
            ffma2(A0, k01.x, P0); ffma2(A1, k01.x, P1);
            ffma2(A2, k01.x, P2); ffma2(A3, k01.x, P3);
            ffma2(A4, k01.x, P4); ffma2(A5, k01.x, P5);
            ffma2(A6, k01.x, P6); ffma2(A7, k01.x, P7);
            ffma2(A0, k01.y, P1); ffma2(A1, k01.y, P2);
            ffma2(A2, k01.y, P3); ffma2(A3, k01.y, P4);
            ffma2(A4, k01.y, P5); ffma2(A5, k01.y, P6);
            ffma2(A6, k01.y, P7); ffma2(A7, k01.y, P8);
            ffma2(A0, k23.x, P2); ffma2(A1, k23.x, P3);
            ffma2(A2, k23.x, P4); ffma2(A3, k23.x, P5);
            ffma2(A4, k23.x, P6); ffma2(A5, k23.x, P7);
            ffma2(A6, k23.x, P8); ffma2(A7, k23.x, P9);
            ffma2(A0, k23.y, P3); ffma2(A1, k23.y, P4);
            ffma2(A2, k23.y, P5); ffma2(A3, k23.y, P6);
            ffma2(A4, k23.y, P7); ffma2(A5, k23.y, P8);
            ffma2(A6, k23.y, P9); ffma2(A7, k23.y, P10);
            // slide window by 4 taps
            float4 nv = *(const float4*)&wp[4 * g + 20];
            float d0, h4, h5, h6, h7;
            upk2(P4, d0, h4); upk2(P5, d0, h5);
            upk2(P6, d0, h6); upk2(P7, d0, h7);
            P0 = P4;  P1 = P5;  P2 = P6;  P3 = P7;
            P4 = P8;  P5 = P9;  P6 = P10; P7 = P11;
            P8  = pk2(h4, nv.x); P9  = pk2(h5, nv.y);
            P10 = pk2(h6, nv.z); P11 = pk2(h7, nv.w);
        }
        {   // last group (taps 204..207 are zero beyond 200; no slide)
            const ulonglong2* kd = (const ulonglong2*)&fkd[8 * (NGROUP - 1)];
            ulonglong2 k01 = kd[0];
            ulonglong2 k23 = kd[1];
            ffma2(A0, k01.x, P0); ffma2(A1, k01.x, P1);
            ffma2(A2, k01.x, P2); ffma2(A3, k01.x, P3);
            ffma2(A4, k01.x, P4); ffma2(A5, k01.x, P5);
            ffma2(A6, k01.x, P6); ffma2(A7, k01.x, P7);
            ffma2(A0, k01.y, P1); ffma2(A1, k01.y, P2);
            ffma2(A2, k01.y, P3); ffma2(A3, k01.y, P4);
            ffma2(A4, k01.y, P5); ffma2(A5, k01.y, P6);
            ffma2(A6, k01.y, P7); ffma2(A7, k01.y, P8);
            ffma2(A0, k23.x, P2); ffma2(A1, k23.x, P3);
            ffma2(A2, k23.x, P4); ffma2(A3, k23.x, P5);
            ffma2(A4, k23.x, P6); ffma2(A5, k23.x, P7);
            ffma2(A6, k23.x, P8); ffma2(A7, k23.x, P9);
            ffma2(A0, k23.y, P3); ffma2(A1, k23.y, P4);
            ffma2(A2, k23.y, P5); ffma2(A3, k23.y, P6);
            ffma2(A4, k23.y, P7); ffma2(A5, k23.y, P8);
            ffma2(A6, k23.y, P9); ffma2(A7, k23.y, P10);
        }
    }
    float lo0, lo1, lo2, lo3, lo4, lo5, lo6, lo7;
    float hi0, hi1, hi2, hi3, hi4, hi5, hi6, hi7;
    upk2(A0, lo0, hi0); upk2(A1, lo1, hi1);
    upk2(A2, lo2, hi2); upk2(A3, lo3, hi3);
    upk2(A4, lo4, hi4); upk2(A5, lo5, hi5);
    upk2(A6, lo6, hi6); upk2(A7, lo7, hi7);

    int t = t0 + 16 * tid;
    if (t + 15 < T_DATA) {
        *(float4*)&dst[s * T_DATA + t]      = make_float4(lo0, lo1, lo2, lo3);
        *(float4*)&dst[s * T_DATA + t + 4]  = make_float4(lo4, lo5, lo6, lo7);
        *(float4*)&dst[s * T_DATA + t + 8]  = make_float4(hi0, hi1, hi2, hi3);
        *(float4*)&dst[s * T_DATA + t + 12] = make_float4(hi4, hi5, hi6, hi7);
    } else {
        float a[16] = {lo0, lo1, lo2, lo3, lo4, lo5, lo6, lo7,
                       hi0, hi1, hi2, hi3, hi4, hi5, hi6, hi7};
        #pragma unroll
        for (int k = 0; k < 16; k++)
            if (t + k < T_DATA) dst[s * T_DATA + t + k] = a[k];
    }
}

// ================= K3: dendritic tree recursion (2 t/thread, float2) ======
__global__ void __launch_bounds__(TREE_THREADS)
k_tree(const float* __restrict__ C_den, const float* __restrict__ W_sub,
       const float* __restrict__ Theta, const float* __restrict__ V_o,
       const float* __restrict__ Cse, const float* __restrict__ Csi,
       float* __restrict__ out_v) {
    __shared__ float cw[SUB_NO * SUB_NO];
    __shared__ float th[SUB_NO];
    const int tid  = threadIdx.x;
    const int gidx = blockIdx.x * TREE_THREADS + tid;

    // fold the C_syn copies into this kernel (grid covers 50048 >= 20000)
    for (int q = gidx; q < SUB_NO * (E_NO + I_NO); q += TREE_BLOCKS * TREE_THREADS) {
        if (q < SUB_NO * E_NO)
            out_v[T_DATA + 2 * SUB_NO * T_NO + q] = Cse[q];
        else
            out_v[T_DATA + 2 * SUB_NO * T_NO + q] = Csi[q - SUB_NO * E_NO];
    }

    for (int idx = tid; idx < SUB_NO * SUB_NO; idx += TREE_THREADS) {
        int c = idx % SUB_NO;
        cw[idx] = C_den[idx] * expf(W_sub[c]);
    }
    if (tid < SUB_NO) th[tid] = Theta[tid];
    __syncthreads();

    const int t = gidx * 2;              // two consecutive t per thread
    if (t >= T_DATA) return;

    float fA[SUB_NO], fB[SUB_NO];
    #pragma unroll
    for (int s = 0; s < SUB_NO; s++) {   // float2 loads: t is even, aligned
        float2 e = *(const float2*)&g_fir_e[s * T_DATA + t];
        float2 i = *(const float2*)&g_fir_i[s * T_DATA + t];
        fA[s] = e.x + i.x;
        fB[s] = e.y + i.y;
    }

    float sA[SUB_NO], sB[SUB_NO];
    #pragma unroll
    for (int s = 0; s < SUB_NO; s++) { sA[s] = 0.f; sB[s] = 0.f; }
    #pragma unroll
    for (int s = SUB_NO - 1; s >= 0; s--) {
        float lA = 0.f, lB = 0.f;
        #pragma unroll
        for (int c = s + 1; c < SUB_NO; c++) {
            float w = cw[s * SUB_NO + c];
            lA = fmaf(w, sA[c], lA);
            lB = fmaf(w, sB[c], lB);
        }
        sA[s] = tanhf(fA[s] + lA + th[s]);
        sB[s] = tanhf(fB[s] + lB + th[s]);
    }
    const float wexp0 = expf(W_sub[0]);
    const float vo    = V_o[0];
    *(float2*)&out_v[t] = make_float2(sA[0] * wexp0 + vo, sB[0] * wexp0 + vo);
}

// ============================= launch ======================================
extern "C" void kernel_launch(void* const* d_in, const int* in_sizes, int n_in,
                              void* d_out, int out_size) {
    const float* S_e   = (const float*)d_in[0];
    const float* S_i   = (const float*)d_in[1];
    const float* Cse   = (const float*)d_in[2];
    const float* Csi   = (const float*)d_in[3];
    const float* Cden  = (const float*)d_in[4];
    const float* Wsyn  = (const float*)d_in[5];
    const float* Tau   = (const float*)d_in[6];
    const float* Delta = (const float*)d_in[7];
    const float* Wsub  = (const float*)d_in[8];
    const float* Theta = (const float*)d_in[9];
    const float* Vo    = (const float*)d_in[10];
    float* out = (float*)d_out;

    cudaFuncSetAttribute(k_agg, cudaFuncAttributeMaxDynamicSharedMemorySize, AGG_SMEM);
    cudaFuncSetAttribute(k_fir, cudaFuncAttributeMaxDynamicSharedMemorySize, FIR_SMEM);

    // output layout: [0,100000) voltage | [100000,108040) filters |
    // [108040,124040) C_syn_e | [124040,128040) C_syn_i
    k_setup<<<4, 512>>>(Cse, Csi, Wsyn, Tau, Delta, out + T_DATA);
    k_agg<<<AGG_GRID, 640, AGG_SMEM>>>(S_e, S_i);
    k_fir<<<2 * SUB_NO * FIR_CHUNKS, FIR_THREADS, FIR_SMEM>>>();
    k_tree<<<TREE_BLOCKS, TREE_THREADS>>>(Cden, Wsub, Theta, Vo, Cse, Csi, out);
}